// round 1
// baseline (speedup 1.0000x reference)
#include <cuda_runtime.h>
#include <math.h>

#define N_NODES 500000
#define N_EDGES 16000000

// ---------------- device scratch (no allocation allowed) ----------------
__device__ int    g_s32[N_EDGES];    // src as int32
__device__ int    g_d32[N_EDGES];    // dst as int32
__device__ float  g_w[N_EDGES];      // masked weight, then overwritten with w_norm
__device__ float  g_deg[N_NODES];    // degree, then overwritten with dinv
__device__ float2 g_y1[N_NODES];     // Tx1 = P(x)
__device__ float2 g_y2[N_NODES];     // P(Tx1)
__device__ int    g_is32;            // 1 if edge_index is int32, 0 if int64

// ---------------- helpers ----------------
__device__ __forceinline__ void red_add_v2(float2* addr, float a, float b) {
    asm volatile("red.global.add.v2.f32 [%0], {%1, %2};"
                 :: "l"(addr), "f"(a), "f"(b) : "memory");
}

// ---------------- kernels ----------------
__global__ void k_zero() {
    int i = blockIdx.x * blockDim.x + threadIdx.x;
    if (i < N_NODES) {
        g_deg[i] = 0.f;
        g_y1[i] = make_float2(0.f, 0.f);
        g_y2[i] = make_float2(0.f, 0.f);
    }
    if (i == 0) g_is32 = 0;
}

// Detect index dtype: if buffer is int64 (values < 2^31, nonneg), every odd
// 32-bit word is a zero high-half. If int32, odd words are random node ids.
__global__ void k_detect(const int* ei32) {
    int t = threadIdx.x;
    int found = 0;
    for (int k = t; k < 4000; k += 256) {
        // positions stay < 31.2M words (< 32M = int32 buffer size)
        if (ei32[(size_t)k * 7800 + 1] != 0) { found = 1; break; }
    }
    if (found) atomicOr(&g_is32, 1);
}

// Pass 1: convert indices to int32, mask self-loops, accumulate degree.
__global__ void k_deg(const void* ei, const float* __restrict__ ew) {
    int i = blockIdx.x * blockDim.x + threadIdx.x;
    if (i >= N_EDGES) return;
    int s, d;
    if (g_is32) {
        const int* p = (const int*)ei;
        s = __ldg(p + i);
        d = __ldg(p + N_EDGES + i);
    } else {
        const long long* p = (const long long*)ei;
        s = (int)__ldg(p + i);
        d = (int)__ldg(p + N_EDGES + i);
    }
    float w = __ldg(ew + i);
    if (s == d) w = 0.f;
    g_s32[i] = s;
    g_d32[i] = d;
    g_w[i] = w;
    if (w != 0.f) atomicAdd(&g_deg[s], w);
}

__global__ void k_dinv() {
    int i = blockIdx.x * blockDim.x + threadIdx.x;
    if (i < N_NODES) {
        float dg = g_deg[i];
        g_deg[i] = (dg > 0.f) ? rsqrtf(dg) : 0.f;
    }
}

// Pass 2: w_norm = -(dinv[s]*w*dinv[d]); y1[d] += w_norm * x[s]
__global__ void k_prop1(const float2* __restrict__ x) {
    int i = blockIdx.x * blockDim.x + threadIdx.x;
    if (i >= N_EDGES) return;
    int s = g_s32[i];
    int d = g_d32[i];
    float w = g_w[i];
    float wn = -(g_deg[s] * w * g_deg[d]);
    g_w[i] = wn;
    if (wn != 0.f) {
        float2 xs = __ldg(&x[s]);
        red_add_v2(&g_y1[d], wn * xs.x, wn * xs.y);
    }
}

// Pass 3: y2[d] += w_norm * y1[s]
__global__ void k_prop2() {
    int i = blockIdx.x * blockDim.x + threadIdx.x;
    if (i >= N_EDGES) return;
    float wn = g_w[i];
    if (wn != 0.f) {
        int s = g_s32[i];
        int d = g_d32[i];
        float2 t = __ldg((const float2*)&g_y1[s]);
        red_add_v2(&g_y2[d], wn * t.x, wn * t.y);
    }
}

// Epilogue: ChebConv combine + GRU-with-zero-H collapse.
__global__ void k_final(const float2* __restrict__ x,
                        const float* __restrict__ Wz,   // Wxz [3,2,1] flat
                        const float* __restrict__ Wh,   // Wxh [3,2,1] flat
                        const float* __restrict__ bxz,
                        const float* __restrict__ bhz,
                        const float* __restrict__ bxh,
                        const float* __restrict__ bhh,
                        float* __restrict__ out) {
    int i = blockIdx.x * blockDim.x + threadIdx.x;
    if (i >= N_NODES) return;
    float2 T0 = __ldg(&x[i]);
    float2 T1 = __ldg((const float2*)&g_y1[i]);
    float2 y2 = __ldg((const float2*)&g_y2[i]);
    float T2x = 2.f * y2.x - T0.x;
    float T2y = 2.f * y2.y - T0.y;

    float Az = T0.x * __ldg(Wz + 0) + T0.y * __ldg(Wz + 1)
             + T1.x * __ldg(Wz + 2) + T1.y * __ldg(Wz + 3)
             + T2x  * __ldg(Wz + 4) + T2y  * __ldg(Wz + 5)
             + __ldg(bxz) + __ldg(bhz);
    float Ah = T0.x * __ldg(Wh + 0) + T0.y * __ldg(Wh + 1)
             + T1.x * __ldg(Wh + 2) + T1.y * __ldg(Wh + 3)
             + T2x  * __ldg(Wh + 4) + T2y  * __ldg(Wh + 5)
             + __ldg(bxh) + __ldg(bhh);

    float z = 1.f / (1.f + expf(-Az));
    out[i] = (1.f - z) * tanhf(Ah);
}

// ---------------- host ----------------
extern "C" void kernel_launch(void* const* d_in, const int* in_sizes, int n_in,
                              void* d_out, int out_size) {
    const float* x  = (const float*)d_in[0];
    const void*  ei = d_in[1];
    const float* ew = (const float*)d_in[2];

    // Resolve input ordering from sizes.
    // dict order:      3:Wxz(6) 4:Wxr(6) 5:Wxh(6) 6:Whz(3) 7:Whr(3) 8:Whh(3)
    //                  9:bxz 10:bhz 11:bxr 12:bhr 13:bxh 14:bhh
    // signature order: 3:Wxz(6) 4:bxz(1) 5:Whz(3) 6:bhz(1) 7:Wxr(6) 8:bxr(1)
    //                  9:Whr(3) 10:bhr(1) 11:Wxh(6) 12:bxh(1) 13:Whh(3) 14:bhh(1)
    int iWxz = 3, iWxh = 5, ibxz = 9, ibhz = 10, ibxh = 13, ibhh = 14; // dict order default
    if (n_in >= 15 && in_sizes[4] == 1) { // signature order
        iWxz = 3; ibxz = 4; ibhz = 6; iWxh = 11; ibxh = 12; ibhh = 14;
    }
    const float* Wz  = (const float*)d_in[iWxz];
    const float* Wh  = (const float*)d_in[iWxh];
    const float* bxz = (const float*)d_in[ibxz];
    const float* bhz = (const float*)d_in[ibhz];
    const float* bxh = (const float*)d_in[ibxh];
    const float* bhh = (const float*)d_in[ibhh];

    const int TPB = 256;
    const int NB = (N_NODES + TPB - 1) / TPB;
    const int EB = (N_EDGES + TPB - 1) / TPB;

    k_zero<<<NB, TPB>>>();
    k_detect<<<1, 256>>>((const int*)ei);
    k_deg<<<EB, TPB>>>(ei, ew);
    k_dinv<<<NB, TPB>>>();
    k_prop1<<<EB, TPB>>>((const float2*)x);
    k_prop2<<<EB, TPB>>>();
    k_final<<<NB, TPB>>>((const float2*)x, Wz, Wh, bxz, bhz, bxh, bhh,
                         (float*)d_out);
}

// round 2
// speedup vs baseline: 1.2357x; 1.2357x over previous
#include <cuda_runtime.h>
#include <math.h>

#define N_NODES 500000
#define N_EDGES 16000000

// ---------------- device scratch (no allocation allowed) ----------------
__device__ int2   g_sd[N_EDGES];     // packed (src,dst) as int32
__device__ float  g_deg[N_NODES];    // degree -> overwritten with dinv
__device__ float2 g_xs[N_NODES];     // dinv * x  (pre-scaled gather array)
__device__ float2 g_t1[N_NODES];     // raw accumulator pass 1
__device__ float2 g_y1[N_NODES];     // dinv * t1 (true Tx1, for epilogue)
__device__ float2 g_g1[N_NODES];     // dinv * y1 (pre-scaled gather array)
__device__ float2 g_t2[N_NODES];     // raw accumulator pass 2
__device__ int    g_is32;            // 1 if edge_index is int32, 0 if int64

// ---------------- helpers ----------------
__device__ __forceinline__ void red_add_v2(float2* addr, float a, float b) {
    asm volatile("red.global.add.v2.f32 [%0], {%1, %2};"
                 :: "l"(addr), "f"(a), "f"(b) : "memory");
}

// ---------------- kernels ----------------
__global__ void k_zero() {
    int i = blockIdx.x * blockDim.x + threadIdx.x;
    if (i < N_NODES) {
        g_deg[i] = 0.f;
        g_t1[i] = make_float2(0.f, 0.f);
        g_t2[i] = make_float2(0.f, 0.f);
    }
    if (i == 0) g_is32 = 0;
}

// Detect index dtype: int64 buffers (nonneg values < 2^31) have zero odd
// 32-bit words; int32 buffers have random node ids there.
__global__ void k_detect(const int* ei32) {
    int t = threadIdx.x;
    int found = 0;
    for (int k = t; k < 4000; k += 256) {
        if (ei32[(size_t)k * 7800 + 1] != 0) { found = 1; break; }
    }
    if (found) atomicOr(&g_is32, 1);
}

// Pass A: convert indices -> packed int2, accumulate weighted degree.
// 4 edges per thread, 128-bit loads.
__global__ void k_deg(const void* __restrict__ ei, const float* __restrict__ ew) {
    int t = blockIdx.x * blockDim.x + threadIdx.x;
    int i = t * 4;
    if (i >= N_EDGES) return;
    int s0, s1, s2, s3, d0, d1, d2, d3;
    if (g_is32) {
        const int* p = (const int*)ei;
        int4 sv = *(const int4*)(p + i);
        int4 dv = *(const int4*)(p + N_EDGES + i);
        s0 = sv.x; s1 = sv.y; s2 = sv.z; s3 = sv.w;
        d0 = dv.x; d1 = dv.y; d2 = dv.z; d3 = dv.w;
    } else {
        const long long* p = (const long long*)ei;
        longlong2 a = *(const longlong2*)(p + i);
        longlong2 b = *(const longlong2*)(p + i + 2);
        longlong2 c = *(const longlong2*)(p + N_EDGES + i);
        longlong2 e = *(const longlong2*)(p + N_EDGES + i + 2);
        s0 = (int)a.x; s1 = (int)a.y; s2 = (int)b.x; s3 = (int)b.y;
        d0 = (int)c.x; d1 = (int)c.y; d2 = (int)e.x; d3 = (int)e.y;
    }
    float4 wv = *(const float4*)(ew + i);
    int s[4] = {s0, s1, s2, s3};
    int d[4] = {d0, d1, d2, d3};
    float w[4] = {wv.x, wv.y, wv.z, wv.w};
    #pragma unroll
    for (int k = 0; k < 4; k++) {
        g_sd[i + k] = make_int2(s[k], d[k]);
        float wm = (s[k] == d[k]) ? 0.f : w[k];
        if (wm != 0.f) atomicAdd(&g_deg[s[k]], wm);
    }
}

// dinv = rsqrt(deg); xs = dinv * x  (fused node pass)
__global__ void k_dinv(const float2* __restrict__ x) {
    int i = blockIdx.x * blockDim.x + threadIdx.x;
    if (i < N_NODES) {
        float dg = g_deg[i];
        float di = (dg > 0.f) ? rsqrtf(dg) : 0.f;
        g_deg[i] = di;
        float2 xi = __ldg(&x[i]);
        g_xs[i] = make_float2(di * xi.x, di * xi.y);
    }
}

// Pass B: t1[d] += -w * xs[s]   (dinv[d] hoisted to node pass)
__global__ void k_prop1(const float* __restrict__ ew) {
    int t = blockIdx.x * blockDim.x + threadIdx.x;
    int i = t * 4;
    if (i >= N_EDGES) return;
    int4 p0 = *(const int4*)&g_sd[i];       // edges i, i+1
    int4 p1 = *(const int4*)&g_sd[i + 2];   // edges i+2, i+3
    float4 wv = *(const float4*)(ew + i);
    int s[4] = {p0.x, p0.z, p1.x, p1.z};
    int d[4] = {p0.y, p0.w, p1.y, p1.w};
    float w[4] = {wv.x, wv.y, wv.z, wv.w};
    #pragma unroll
    for (int k = 0; k < 4; k++) {
        float wm = (s[k] == d[k]) ? 0.f : w[k];
        if (wm != 0.f) {
            float2 xs = __ldg(&g_xs[s[k]]);
            red_add_v2(&g_t1[d[k]], -wm * xs.x, -wm * xs.y);
        }
    }
}

// Node pass: y1 = dinv*t1 (true Tx1); g1 = dinv*y1 (pre-scaled for pass C)
__global__ void k_scale2() {
    int i = blockIdx.x * blockDim.x + threadIdx.x;
    if (i < N_NODES) {
        float di = g_deg[i];
        float2 t1 = g_t1[i];
        float2 y1 = make_float2(di * t1.x, di * t1.y);
        g_y1[i] = y1;
        g_g1[i] = make_float2(di * y1.x, di * y1.y);
    }
}

// Pass C: t2[d] += -w * g1[s]
__global__ void k_prop2(const float* __restrict__ ew) {
    int t = blockIdx.x * blockDim.x + threadIdx.x;
    int i = t * 4;
    if (i >= N_EDGES) return;
    int4 p0 = *(const int4*)&g_sd[i];
    int4 p1 = *(const int4*)&g_sd[i + 2];
    float4 wv = *(const float4*)(ew + i);
    int s[4] = {p0.x, p0.z, p1.x, p1.z};
    int d[4] = {p0.y, p0.w, p1.y, p1.w};
    float w[4] = {wv.x, wv.y, wv.z, wv.w};
    #pragma unroll
    for (int k = 0; k < 4; k++) {
        float wm = (s[k] == d[k]) ? 0.f : w[k];
        if (wm != 0.f) {
            float2 g1 = __ldg(&g_g1[s[k]]);
            red_add_v2(&g_t2[d[k]], -wm * g1.x, -wm * g1.y);
        }
    }
}

// Epilogue: y2 = dinv*t2; ChebConv combine + GRU-with-zero-H collapse.
__global__ void k_final(const float2* __restrict__ x,
                        const float* __restrict__ Wz,
                        const float* __restrict__ Wh,
                        const float* __restrict__ bxz,
                        const float* __restrict__ bhz,
                        const float* __restrict__ bxh,
                        const float* __restrict__ bhh,
                        float* __restrict__ out) {
    int i = blockIdx.x * blockDim.x + threadIdx.x;
    if (i >= N_NODES) return;
    float di = g_deg[i];
    float2 T0 = __ldg(&x[i]);
    float2 T1 = g_y1[i];
    float2 t2 = g_t2[i];
    float T2x = 2.f * (di * t2.x) - T0.x;
    float T2y = 2.f * (di * t2.y) - T0.y;

    float Az = T0.x * __ldg(Wz + 0) + T0.y * __ldg(Wz + 1)
             + T1.x * __ldg(Wz + 2) + T1.y * __ldg(Wz + 3)
             + T2x  * __ldg(Wz + 4) + T2y  * __ldg(Wz + 5)
             + __ldg(bxz) + __ldg(bhz);
    float Ah = T0.x * __ldg(Wh + 0) + T0.y * __ldg(Wh + 1)
             + T1.x * __ldg(Wh + 2) + T1.y * __ldg(Wh + 3)
             + T2x  * __ldg(Wh + 4) + T2y  * __ldg(Wh + 5)
             + __ldg(bxh) + __ldg(bhh);

    float z = 1.f / (1.f + expf(-Az));
    out[i] = (1.f - z) * tanhf(Ah);
}

// ---------------- host ----------------
extern "C" void kernel_launch(void* const* d_in, const int* in_sizes, int n_in,
                              void* d_out, int out_size) {
    const float* x  = (const float*)d_in[0];
    const void*  ei = d_in[1];
    const float* ew = (const float*)d_in[2];

    int iWxz = 3, iWxh = 5, ibxz = 9, ibhz = 10, ibxh = 13, ibhh = 14; // dict order
    if (n_in >= 15 && in_sizes[4] == 1) { // signature order
        iWxz = 3; ibxz = 4; ibhz = 6; iWxh = 11; ibxh = 12; ibhh = 14;
    }
    const float* Wz  = (const float*)d_in[iWxz];
    const float* Wh  = (const float*)d_in[iWxh];
    const float* bxz = (const float*)d_in[ibxz];
    const float* bhz = (const float*)d_in[ibhz];
    const float* bxh = (const float*)d_in[ibxh];
    const float* bhh = (const float*)d_in[ibhh];

    const int TPB = 256;
    const int NB = (N_NODES + TPB - 1) / TPB;
    const int EB4 = (N_EDGES / 4 + TPB - 1) / TPB;

    k_zero<<<NB, TPB>>>();
    k_detect<<<1, 256>>>((const int*)ei);
    k_deg<<<EB4, TPB>>>(ei, ew);
    k_dinv<<<NB, TPB>>>((const float2*)x);
    k_prop1<<<EB4, TPB>>>(ew);
    k_scale2<<<NB, TPB>>>();
    k_prop2<<<EB4, TPB>>>(ew);
    k_final<<<NB, TPB>>>((const float2*)x, Wz, Wh, bxz, bhz, bxh, bhh,
                         (float*)d_out);
}

// round 3
// speedup vs baseline: 1.3046x; 1.0558x over previous
#include <cuda_runtime.h>
#include <math.h>

#define N_NODES 500000
#define N_EDGES 16000000

// ---------------- device scratch (no allocation allowed) ----------------
__device__ unsigned long long g_rec[N_EDGES]; // s:19 | d:19 | top26(-w):26
__device__ float  g_deg[N_NODES];    // degree -> overwritten with dinv
__device__ float2 g_xs[N_NODES];     // dinv * x  (pre-scaled gather array)
__device__ float2 g_t1[N_NODES];     // raw accumulator pass 1
__device__ float2 g_y1[N_NODES];     // dinv * t1 (true Tx1, for epilogue)
__device__ float2 g_g1[N_NODES];     // dinv * y1 (pre-scaled gather array)
__device__ float2 g_t2[N_NODES];     // raw accumulator pass 2
__device__ int    g_is32;            // 1 if edge_index is int32, 0 if int64

// ---------------- helpers ----------------
__device__ __forceinline__ void red_add_v2(float2* addr, float a, float b) {
    asm volatile("red.global.add.v2.f32 [%0], {%1, %2};"
                 :: "l"(addr), "f"(a), "f"(b) : "memory");
}

__device__ __forceinline__ unsigned long long pack_rec(int s, int d, float w) {
    // w already masked (0 for self-loops); store bits of (-w), top 26 bits.
    unsigned int wb = 0u;
    if (w != 0.f) wb = __float_as_uint(-w);
    return (unsigned long long)(unsigned)s
         | ((unsigned long long)(unsigned)d << 19)
         | ((unsigned long long)(wb >> 6) << 38);
}

// ---------------- kernels ----------------
// Detect index dtype: int64 buffers (nonneg values < 2^31) have zero odd
// 32-bit words; int32 buffers have random node ids there. Also init g_is32.
__global__ void k_detect(const int* ei32) {
    if (threadIdx.x == 0) g_is32 = 0;
    __syncthreads();
    int found = 0;
    for (int k = threadIdx.x; k < 4000; k += 256) {
        if (ei32[(size_t)k * 7800 + 1] != 0) { found = 1; break; }
    }
    if (found) atomicOr(&g_is32, 1);
}

// Pass A: build packed records, accumulate weighted degree. 8 edges/thread.
__global__ void k_deg(const void* __restrict__ ei, const float* __restrict__ ew) {
    int t = blockIdx.x * blockDim.x + threadIdx.x;
    int i = t * 8;
    if (i >= N_EDGES) return;
    int s[8], d[8];
    if (g_is32) {
        const int4* ps = (const int4*)((const int*)ei + i);
        const int4* pd = (const int4*)((const int*)ei + N_EDGES + i);
        int4 a = ps[0], b = ps[1], c = pd[0], e = pd[1];
        s[0]=a.x; s[1]=a.y; s[2]=a.z; s[3]=a.w; s[4]=b.x; s[5]=b.y; s[6]=b.z; s[7]=b.w;
        d[0]=c.x; d[1]=c.y; d[2]=c.z; d[3]=c.w; d[4]=e.x; d[5]=e.y; d[6]=e.z; d[7]=e.w;
    } else {
        const longlong2* ps = (const longlong2*)((const long long*)ei + i);
        const longlong2* pd = (const longlong2*)((const long long*)ei + N_EDGES + i);
        #pragma unroll
        for (int k = 0; k < 4; k++) {
            longlong2 a = ps[k]; s[2*k] = (int)a.x; s[2*k+1] = (int)a.y;
            longlong2 b = pd[k]; d[2*k] = (int)b.x; d[2*k+1] = (int)b.y;
        }
    }
    float4 w0 = *(const float4*)(ew + i);
    float4 w1 = *(const float4*)(ew + i + 4);
    float w[8] = {w0.x, w0.y, w0.z, w0.w, w1.x, w1.y, w1.z, w1.w};
    unsigned long long r[8];
    #pragma unroll
    for (int k = 0; k < 8; k++) {
        float wm = (s[k] == d[k]) ? 0.f : w[k];
        r[k] = pack_rec(s[k], d[k], wm);
        if (wm != 0.f) atomicAdd(&g_deg[s[k]], wm);
    }
    ulonglong2* out = (ulonglong2*)&g_rec[i];
    out[0] = make_ulonglong2(r[0], r[1]);
    out[1] = make_ulonglong2(r[2], r[3]);
    out[2] = make_ulonglong2(r[4], r[5]);
    out[3] = make_ulonglong2(r[6], r[7]);
}

// dinv = rsqrt(deg); xs = dinv * x   (2 nodes/thread)
__global__ void k_dinv(const float4* __restrict__ x) {
    int t = blockIdx.x * blockDim.x + threadIdx.x;
    int i = t * 2;
    if (i >= N_NODES) return;
    float2 dg = *(const float2*)&g_deg[i];
    float d0 = (dg.x > 0.f) ? rsqrtf(dg.x) : 0.f;
    float d1 = (dg.y > 0.f) ? rsqrtf(dg.y) : 0.f;
    *(float2*)&g_deg[i] = make_float2(d0, d1);
    float4 xv = __ldg(&x[t]);
    *(float4*)&g_xs[i] = make_float4(d0 * xv.x, d0 * xv.y, d1 * xv.z, d1 * xv.w);
}

// Pass B: t1[d] += -w * xs[s]   (8 edges/thread)
__global__ void k_prop1() {
    int t = blockIdx.x * blockDim.x + threadIdx.x;
    int i = t * 8;
    if (i >= N_EDGES) return;
    const ulonglong2* in = (const ulonglong2*)&g_rec[i];
    ulonglong2 v0 = in[0], v1 = in[1], v2 = in[2], v3 = in[3];
    unsigned long long r[8] = {v0.x, v0.y, v1.x, v1.y, v2.x, v2.y, v3.x, v3.y};
    #pragma unroll
    for (int k = 0; k < 8; k++) {
        unsigned long long rec = r[k];
        unsigned int wb = (unsigned int)(rec >> 38) << 6;
        if (wb) {
            int s = (int)(rec & 0x7FFFFu);
            int d = (int)((rec >> 19) & 0x7FFFFu);
            float nw = __uint_as_float(wb);       // = -w
            float2 xs = __ldg(&g_xs[s]);
            red_add_v2(&g_t1[d], nw * xs.x, nw * xs.y);
        }
    }
}

// Node pass: y1 = dinv*t1; g1 = dinv*y1   (2 nodes/thread)
__global__ void k_scale2() {
    int t = blockIdx.x * blockDim.x + threadIdx.x;
    int i = t * 2;
    if (i >= N_NODES) return;
    float2 di = *(const float2*)&g_deg[i];
    float4 t1 = *(const float4*)&g_t1[i];
    float4 y1 = make_float4(di.x * t1.x, di.x * t1.y, di.y * t1.z, di.y * t1.w);
    *(float4*)&g_y1[i] = y1;
    *(float4*)&g_g1[i] = make_float4(di.x * y1.x, di.x * y1.y, di.y * y1.z, di.y * y1.w);
}

// Pass C: t2[d] += -w * g1[s]   (8 edges/thread)
__global__ void k_prop2() {
    int t = blockIdx.x * blockDim.x + threadIdx.x;
    int i = t * 8;
    if (i >= N_EDGES) return;
    const ulonglong2* in = (const ulonglong2*)&g_rec[i];
    ulonglong2 v0 = in[0], v1 = in[1], v2 = in[2], v3 = in[3];
    unsigned long long r[8] = {v0.x, v0.y, v1.x, v1.y, v2.x, v2.y, v3.x, v3.y};
    #pragma unroll
    for (int k = 0; k < 8; k++) {
        unsigned long long rec = r[k];
        unsigned int wb = (unsigned int)(rec >> 38) << 6;
        if (wb) {
            int s = (int)(rec & 0x7FFFFu);
            int d = (int)((rec >> 19) & 0x7FFFFu);
            float nw = __uint_as_float(wb);
            float2 g1 = __ldg(&g_g1[s]);
            red_add_v2(&g_t2[d], nw * g1.x, nw * g1.y);
        }
    }
}

// Epilogue: y2 = dinv*t2; ChebConv combine + GRU-with-zero-H collapse.
__global__ void k_final(const float2* __restrict__ x,
                        const float* __restrict__ Wz,
                        const float* __restrict__ Wh,
                        const float* __restrict__ bxz,
                        const float* __restrict__ bhz,
                        const float* __restrict__ bxh,
                        const float* __restrict__ bhh,
                        float* __restrict__ out) {
    int i = blockIdx.x * blockDim.x + threadIdx.x;
    if (i >= N_NODES) return;
    float di = g_deg[i];
    float2 T0 = __ldg(&x[i]);
    float2 T1 = g_y1[i];
    float2 t2 = g_t2[i];
    float T2x = 2.f * (di * t2.x) - T0.x;
    float T2y = 2.f * (di * t2.y) - T0.y;

    float Az = T0.x * __ldg(Wz + 0) + T0.y * __ldg(Wz + 1)
             + T1.x * __ldg(Wz + 2) + T1.y * __ldg(Wz + 3)
             + T2x  * __ldg(Wz + 4) + T2y  * __ldg(Wz + 5)
             + __ldg(bxz) + __ldg(bhz);
    float Ah = T0.x * __ldg(Wh + 0) + T0.y * __ldg(Wh + 1)
             + T1.x * __ldg(Wh + 2) + T1.y * __ldg(Wh + 3)
             + T2x  * __ldg(Wh + 4) + T2y  * __ldg(Wh + 5)
             + __ldg(bxh) + __ldg(bhh);

    float z = 1.f / (1.f + expf(-Az));
    out[i] = (1.f - z) * tanhf(Ah);
}

// ---------------- host ----------------
extern "C" void kernel_launch(void* const* d_in, const int* in_sizes, int n_in,
                              void* d_out, int out_size) {
    const float* x  = (const float*)d_in[0];
    const void*  ei = d_in[1];
    const float* ew = (const float*)d_in[2];

    int iWxz = 3, iWxh = 5, ibxz = 9, ibhz = 10, ibxh = 13, ibhh = 14; // dict order
    if (n_in >= 15 && in_sizes[4] == 1) { // signature order
        iWxz = 3; ibxz = 4; ibhz = 6; iWxh = 11; ibxh = 12; ibhh = 14;
    }
    const float* Wz  = (const float*)d_in[iWxz];
    const float* Wh  = (const float*)d_in[iWxh];
    const float* bxz = (const float*)d_in[ibxz];
    const float* bhz = (const float*)d_in[ibhz];
    const float* bxh = (const float*)d_in[ibxh];
    const float* bhh = (const float*)d_in[ibhh];

    const int TPB = 256;
    const int NB  = (N_NODES + TPB - 1) / TPB;
    const int NB2 = (N_NODES / 2 + TPB - 1) / TPB;
    const int EB8 = (N_EDGES / 8 + TPB - 1) / TPB;

    // Zero accumulators via memset nodes (graph-capturable).
    void *p_deg, *p_t1, *p_t2;
    cudaGetSymbolAddress(&p_deg, g_deg);
    cudaGetSymbolAddress(&p_t1,  g_t1);
    cudaGetSymbolAddress(&p_t2,  g_t2);
    cudaMemsetAsync(p_deg, 0, N_NODES * sizeof(float), 0);
    cudaMemsetAsync(p_t1,  0, N_NODES * sizeof(float2), 0);
    cudaMemsetAsync(p_t2,  0, N_NODES * sizeof(float2), 0);

    k_detect<<<1, 256>>>((const int*)ei);
    k_deg<<<EB8, TPB>>>(ei, ew);
    k_dinv<<<NB2, TPB>>>((const float4*)x);
    k_prop1<<<EB8, TPB>>>();
    k_scale2<<<NB2, TPB>>>();
    k_prop2<<<EB8, TPB>>>();
    k_final<<<NB, TPB>>>((const float2*)x, Wz, Wh, bxz, bhz, bxh, bhh,
                         (float*)d_out);
}

// round 4
// speedup vs baseline: 1.3456x; 1.0314x over previous
#include <cuda_runtime.h>
#include <math.h>

#define N_NODES 500000
#define N_EDGES 16000000

#define BSH     10                       // bucket = src >> 10
#define BWIN    (1 << BSH)               // 1024 nodes per bucket
#define NBKT    ((N_NODES + BWIN - 1) >> BSH)   // 489
#define CAP     49152                    // per-bucket record capacity (mean 32.7K)
#define NSLICE  8                        // blocks per bucket in binned passes
#define EPB     4096                     // edges per scatter block
#define SCB     ((N_EDGES + EPB - 1) / EPB)     // 3907
#define OVF     (1 << 20)

// ---------------- device scratch (no allocation allowed) ----------------
__device__ unsigned long long g_rec2[(size_t)NBKT * CAP]; // binned: s:19|d:19|top26(-w):26
__device__ unsigned long long g_ovf[OVF];
__device__ unsigned int       g_ovf_cnt;
__device__ unsigned int       g_bcur[NBKT];   // absolute write cursors
__device__ float  g_deg[N_NODES];    // degree -> overwritten with dinv
__device__ float2 g_xs[N_NODES];     // dinv * x
__device__ float2 g_t1[N_NODES];     // raw accumulator pass 1
__device__ float2 g_y1[N_NODES];     // dinv * t1 (true Tx1)
__device__ float2 g_g1[N_NODES];     // dinv * y1
__device__ float2 g_t2[N_NODES];     // raw accumulator pass 2
__device__ int    g_is32;

// ---------------- helpers ----------------
__device__ __forceinline__ void red_add_v2(float2* addr, float a, float b) {
    asm volatile("red.global.add.v2.f32 [%0], {%1, %2};"
                 :: "l"(addr), "f"(a), "f"(b) : "memory");
}

__device__ __forceinline__ unsigned long long pack_rec(int s, int d, float w) {
    unsigned int wb = 0u;
    if (w != 0.f) wb = __float_as_uint(-w);
    return (unsigned long long)(unsigned)s
         | ((unsigned long long)(unsigned)d << 19)
         | ((unsigned long long)(wb >> 6) << 38);
}

__device__ __forceinline__ void spill_rec(unsigned long long rec) {
    unsigned p = atomicAdd(&g_ovf_cnt, 1u);
    if (p < OVF) g_ovf[p] = rec;
}

// ---------------- kernels ----------------
__global__ void k_initcur() {
    int i = blockIdx.x * blockDim.x + threadIdx.x;
    if (i < NBKT) g_bcur[i] = (unsigned)(i * CAP);
    if (i == 0) g_ovf_cnt = 0u;
}

// Detect index dtype (int64 high halves are zero for nonneg ids < 2^31).
__global__ void k_detect(const int* ei32) {
    if (threadIdx.x == 0) g_is32 = 0;
    __syncthreads();
    int found = 0;
    for (int k = threadIdx.x; k < 4000; k += 256) {
        if (ei32[(size_t)k * 7800 + 1] != 0) { found = 1; break; }
    }
    if (found) atomicOr(&g_is32, 1);
}

// Counting-sort scatter: bin edges by src bucket into g_rec2 (coalesced runs).
__global__ void k_scatter(const void* __restrict__ ei, const float* __restrict__ ew) {
    __shared__ unsigned int sh_hist[512];       // hist, then local running cursor
    __shared__ unsigned int sh_scan[256];
    __shared__ int          sh_delta[512];
    __shared__ unsigned long long sh_stage[EPB];

    const int tid = threadIdx.x;
    const int base = blockIdx.x * EPB;
    const int is32 = g_is32;

    for (int i = tid; i < 512; i += 256) sh_hist[i] = 0u;
    __syncthreads();

    // Phase 1: histogram of src buckets.
    #pragma unroll
    for (int k = 0; k < EPB / 256; k++) {
        int e = base + k * 256 + tid;
        if (e < N_EDGES) {
            int s = is32 ? __ldg((const int*)ei + e)
                         : (int)__ldg((const long long*)ei + e);
            atomicAdd(&sh_hist[s >> BSH], 1u);
        }
    }
    __syncthreads();

    // Phase 2: exclusive scan over 512 (2 buckets/thread).
    unsigned a0 = sh_hist[2 * tid], a1 = sh_hist[2 * tid + 1];
    sh_scan[tid] = a0 + a1;
    __syncthreads();
    for (int off = 1; off < 256; off <<= 1) {
        unsigned v = sh_scan[tid];
        unsigned add = (tid >= off) ? sh_scan[tid - off] : 0u;
        __syncthreads();
        sh_scan[tid] = v + add;
        __syncthreads();
    }
    unsigned total = sh_scan[255];
    unsigned excl = (tid == 0) ? 0u : sh_scan[tid - 1];
    unsigned p0 = excl, p1 = excl + a0;

    // Phase 3: reserve global space, compute local->global deltas.
    int b0 = 2 * tid, b1 = 2 * tid + 1;
    if (a0) { unsigned g = atomicAdd(&g_bcur[b0], a0); sh_delta[b0] = (int)g - (int)p0; }
    if (a1) { unsigned g = atomicAdd(&g_bcur[b1], a1); sh_delta[b1] = (int)g - (int)p1; }
    sh_hist[b0] = p0;   // reuse hist as local running cursors
    sh_hist[b1] = p1;
    __syncthreads();

    // Phase 4: stage records sorted by bucket.
    #pragma unroll
    for (int k = 0; k < EPB / 256; k++) {
        int e = base + k * 256 + tid;
        if (e < N_EDGES) {
            int s, d;
            if (is32) {
                const int* p = (const int*)ei;
                s = __ldg(p + e); d = __ldg(p + N_EDGES + e);
            } else {
                const long long* p = (const long long*)ei;
                s = (int)__ldg(p + e); d = (int)__ldg(p + N_EDGES + e);
            }
            float w = __ldg(ew + e);
            if (s == d) w = 0.f;
            unsigned p = atomicAdd(&sh_hist[s >> BSH], 1u);
            sh_stage[p] = pack_rec(s, d, w);
        }
    }
    __syncthreads();

    // Phase 5: coalesced write-out (runs per bucket are contiguous).
    for (unsigned p = tid; p < total; p += 256) {
        unsigned long long rec = sh_stage[p];
        int s = (int)(rec & 0x7FFFFu);
        int b = s >> BSH;
        unsigned gpos = (unsigned)((int)p + sh_delta[b]);
        if (gpos < (unsigned)(b + 1) * CAP) g_rec2[gpos] = rec;
        else spill_rec(rec);
    }
}

// Degree: smem window accumulation per bucket, coalesced flush.
__global__ void k_deg2() {
    __shared__ float sh[BWIN];
    const int tid = threadIdx.x;
    const int b = blockIdx.x / NSLICE;
    const int j = blockIdx.x % NSLICE;
    unsigned cnt = g_bcur[b] - (unsigned)(b * CAP);
    if (cnt > CAP) cnt = CAP;
    unsigned chunk = (cnt + NSLICE - 1) / NSLICE;
    unsigned s0 = j * chunk, s1 = min(cnt, s0 + chunk);

    for (int i = tid; i < BWIN; i += 256) sh[i] = 0.f;
    __syncthreads();

    const unsigned long long* base = &g_rec2[(size_t)b * CAP];
    for (unsigned i = s0 + tid; i < s1; i += 256) {
        unsigned long long rec = base[i];
        unsigned wb = (unsigned)(rec >> 38) << 6;
        if (wb) {
            int sl = (int)(rec & 0x7FFFFu) - (b << BSH);
            atomicAdd(&sh[sl], -__uint_as_float(wb));   // rec holds -w
        }
    }
    __syncthreads();
    for (int i = tid; i < BWIN; i += 256) {
        float v = sh[i];
        int node = (b << BSH) + i;
        if (v != 0.f && node < N_NODES) atomicAdd(&g_deg[node], v);
    }
    // Overflow records: direct global reds (normally empty).
    if (blockIdx.x == gridDim.x - 1) {
        unsigned n = g_ovf_cnt; if (n > OVF) n = OVF;
        for (unsigned i = tid; i < n; i += 256) {
            unsigned long long rec = g_ovf[i];
            unsigned wb = (unsigned)(rec >> 38) << 6;
            if (wb) atomicAdd(&g_deg[rec & 0x7FFFFu], -__uint_as_float(wb));
        }
    }
}

// dinv = rsqrt(deg); xs = dinv * x   (2 nodes/thread)
__global__ void k_dinv(const float4* __restrict__ x) {
    int t = blockIdx.x * blockDim.x + threadIdx.x;
    int i = t * 2;
    if (i >= N_NODES) return;
    float2 dg = *(const float2*)&g_deg[i];
    float d0 = (dg.x > 0.f) ? rsqrtf(dg.x) : 0.f;
    float d1 = (dg.y > 0.f) ? rsqrtf(dg.y) : 0.f;
    *(float2*)&g_deg[i] = make_float2(d0, d1);
    float4 xv = __ldg(&x[t]);
    *(float4*)&g_xs[i] = make_float4(d0 * xv.x, d0 * xv.y, d1 * xv.z, d1 * xv.w);
}

// Prop pass over binned records: gather window is L1-resident.
__global__ void k_prop1() {
    const int tid = threadIdx.x;
    const int b = blockIdx.x / NSLICE;
    const int j = blockIdx.x % NSLICE;
    unsigned cnt = g_bcur[b] - (unsigned)(b * CAP);
    if (cnt > CAP) cnt = CAP;
    unsigned chunk = (cnt + NSLICE - 1) / NSLICE;
    unsigned s0 = j * chunk, s1 = min(cnt, s0 + chunk);
    const unsigned long long* base = &g_rec2[(size_t)b * CAP];
    for (unsigned i = s0 + tid; i < s1; i += 256) {
        unsigned long long rec = base[i];
        unsigned wb = (unsigned)(rec >> 38) << 6;
        if (wb) {
            int s = (int)(rec & 0x7FFFFu);
            int d = (int)((rec >> 19) & 0x7FFFFu);
            float nw = __uint_as_float(wb);      // = -w
            float2 xs = __ldg(&g_xs[s]);
            red_add_v2(&g_t1[d], nw * xs.x, nw * xs.y);
        }
    }
    if (blockIdx.x == gridDim.x - 1) {
        unsigned n = g_ovf_cnt; if (n > OVF) n = OVF;
        for (unsigned i = tid; i < n; i += 256) {
            unsigned long long rec = g_ovf[i];
            unsigned wb = (unsigned)(rec >> 38) << 6;
            if (wb) {
                int s = (int)(rec & 0x7FFFFu);
                int d = (int)((rec >> 19) & 0x7FFFFu);
                float nw = __uint_as_float(wb);
                float2 xs = __ldg(&g_xs[s]);
                red_add_v2(&g_t1[d], nw * xs.x, nw * xs.y);
            }
        }
    }
}

__global__ void k_scale2() {
    int t = blockIdx.x * blockDim.x + threadIdx.x;
    int i = t * 2;
    if (i >= N_NODES) return;
    float2 di = *(const float2*)&g_deg[i];
    float4 t1 = *(const float4*)&g_t1[i];
    float4 y1 = make_float4(di.x * t1.x, di.x * t1.y, di.y * t1.z, di.y * t1.w);
    *(float4*)&g_y1[i] = y1;
    *(float4*)&g_g1[i] = make_float4(di.x * y1.x, di.x * y1.y, di.y * y1.z, di.y * y1.w);
}

__global__ void k_prop2() {
    const int tid = threadIdx.x;
    const int b = blockIdx.x / NSLICE;
    const int j = blockIdx.x % NSLICE;
    unsigned cnt = g_bcur[b] - (unsigned)(b * CAP);
    if (cnt > CAP) cnt = CAP;
    unsigned chunk = (cnt + NSLICE - 1) / NSLICE;
    unsigned s0 = j * chunk, s1 = min(cnt, s0 + chunk);
    const unsigned long long* base = &g_rec2[(size_t)b * CAP];
    for (unsigned i = s0 + tid; i < s1; i += 256) {
        unsigned long long rec = base[i];
        unsigned wb = (unsigned)(rec >> 38) << 6;
        if (wb) {
            int s = (int)(rec & 0x7FFFFu);
            int d = (int)((rec >> 19) & 0x7FFFFu);
            float nw = __uint_as_float(wb);
            float2 g1 = __ldg(&g_g1[s]);
            red_add_v2(&g_t2[d], nw * g1.x, nw * g1.y);
        }
    }
    if (blockIdx.x == gridDim.x - 1) {
        unsigned n = g_ovf_cnt; if (n > OVF) n = OVF;
        for (unsigned i = tid; i < n; i += 256) {
            unsigned long long rec = g_ovf[i];
            unsigned wb = (unsigned)(rec >> 38) << 6;
            if (wb) {
                int s = (int)(rec & 0x7FFFFu);
                int d = (int)((rec >> 19) & 0x7FFFFu);
                float nw = __uint_as_float(wb);
                float2 g1 = __ldg(&g_g1[s]);
                red_add_v2(&g_t2[d], nw * g1.x, nw * g1.y);
            }
        }
    }
}

__global__ void k_final(const float2* __restrict__ x,
                        const float* __restrict__ Wz,
                        const float* __restrict__ Wh,
                        const float* __restrict__ bxz,
                        const float* __restrict__ bhz,
                        const float* __restrict__ bxh,
                        const float* __restrict__ bhh,
                        float* __restrict__ out) {
    int i = blockIdx.x * blockDim.x + threadIdx.x;
    if (i >= N_NODES) return;
    float di = g_deg[i];
    float2 T0 = __ldg(&x[i]);
    float2 T1 = g_y1[i];
    float2 t2 = g_t2[i];
    float T2x = 2.f * (di * t2.x) - T0.x;
    float T2y = 2.f * (di * t2.y) - T0.y;

    float Az = T0.x * __ldg(Wz + 0) + T0.y * __ldg(Wz + 1)
             + T1.x * __ldg(Wz + 2) + T1.y * __ldg(Wz + 3)
             + T2x  * __ldg(Wz + 4) + T2y  * __ldg(Wz + 5)
             + __ldg(bxz) + __ldg(bhz);
    float Ah = T0.x * __ldg(Wh + 0) + T0.y * __ldg(Wh + 1)
             + T1.x * __ldg(Wh + 2) + T1.y * __ldg(Wh + 3)
             + T2x  * __ldg(Wh + 4) + T2y  * __ldg(Wh + 5)
             + __ldg(bxh) + __ldg(bhh);

    float z = 1.f / (1.f + expf(-Az));
    out[i] = (1.f - z) * tanhf(Ah);
}

// ---------------- host ----------------
extern "C" void kernel_launch(void* const* d_in, const int* in_sizes, int n_in,
                              void* d_out, int out_size) {
    const float* x  = (const float*)d_in[0];
    const void*  ei = d_in[1];
    const float* ew = (const float*)d_in[2];

    int iWxz = 3, iWxh = 5, ibxz = 9, ibhz = 10, ibxh = 13, ibhh = 14; // dict order
    if (n_in >= 15 && in_sizes[4] == 1) { // signature order
        iWxz = 3; ibxz = 4; ibhz = 6; iWxh = 11; ibxh = 12; ibhh = 14;
    }
    const float* Wz  = (const float*)d_in[iWxz];
    const float* Wh  = (const float*)d_in[iWxh];
    const float* bxz = (const float*)d_in[ibxz];
    const float* bhz = (const float*)d_in[ibhz];
    const float* bxh = (const float*)d_in[ibxh];
    const float* bhh = (const float*)d_in[ibhh];

    const int TPB = 256;
    const int NB  = (N_NODES + TPB - 1) / TPB;
    const int NB2 = (N_NODES / 2 + TPB - 1) / TPB;

    void *p_deg, *p_t1, *p_t2;
    cudaGetSymbolAddress(&p_deg, g_deg);
    cudaGetSymbolAddress(&p_t1,  g_t1);
    cudaGetSymbolAddress(&p_t2,  g_t2);
    cudaMemsetAsync(p_deg, 0, N_NODES * sizeof(float), 0);
    cudaMemsetAsync(p_t1,  0, N_NODES * sizeof(float2), 0);
    cudaMemsetAsync(p_t2,  0, N_NODES * sizeof(float2), 0);

    k_initcur<<<(NBKT + TPB - 1) / TPB, TPB>>>();
    k_detect<<<1, 256>>>((const int*)ei);
    k_scatter<<<SCB, TPB>>>(ei, ew);
    k_deg2<<<NBKT * NSLICE, TPB>>>();
    k_dinv<<<NB2, TPB>>>((const float4*)x);
    k_prop1<<<NBKT * NSLICE, TPB>>>();
    k_scale2<<<NB2, TPB>>>();
    k_prop2<<<NBKT * NSLICE, TPB>>>();
    k_final<<<NB, TPB>>>((const float2*)x, Wz, Wh, bxz, bhz, bxh, bhh,
                         (float*)d_out);
}

// round 5
// speedup vs baseline: 1.4879x; 1.1057x over previous
#include <cuda_runtime.h>
#include <math.h>

#define N_NODES 500000
#define N_EDGES 16000000

#define BSH     10                       // bucket = src >> 10
#define BWIN    (1 << BSH)               // 1024 nodes per bucket
#define NBKT    ((N_NODES + BWIN - 1) >> BSH)   // 489
#define CAP     49152                    // per-bucket capacity (mean 32.7K, ~90 sigma)
#define NSLICE  8                        // blocks per bucket in binned passes
#define EPB     4096                     // edges per scatter block
#define SCB     ((N_EDGES + EPB - 1) / EPB)     // 3907
#define OVF     (1 << 20)

// ---------------- device scratch (no allocation allowed) ----------------
__device__ unsigned long long g_rec2[(size_t)NBKT * CAP]; // s:19|d:19|top26(-w):26
__device__ unsigned long long g_ovf[OVF];
__device__ unsigned int       g_ovf_cnt;
__device__ unsigned int       g_bcur[NBKT];   // absolute write cursors
__device__ float  g_deg[N_NODES];    // degree -> overwritten with dinv
__device__ float2 g_xs[N_NODES];     // dinv * x
__device__ float2 g_t1[N_NODES];     // raw accumulator pass 1
__device__ float2 g_y1[N_NODES];     // dinv * t1 (true Tx1)
__device__ float2 g_g1[N_NODES];     // dinv * y1
__device__ float2 g_t2[N_NODES];     // raw accumulator pass 2
__device__ int    g_is32;

// ---------------- helpers ----------------
__device__ __forceinline__ void red_add_v2(float2* addr, float a, float b) {
    asm volatile("red.global.add.v2.f32 [%0], {%1, %2};"
                 :: "l"(addr), "f"(a), "f"(b) : "memory");
}

__device__ __forceinline__ unsigned long long pack_rec(int s, int d, float w) {
    unsigned int wb = 0u;
    if (w != 0.f) wb = __float_as_uint(-w);
    return (unsigned long long)(unsigned)s
         | ((unsigned long long)(unsigned)d << 19)
         | ((unsigned long long)(wb >> 6) << 38);
}

__device__ __forceinline__ void spill_rec(unsigned long long rec) {
    unsigned p = atomicAdd(&g_ovf_cnt, 1u);
    if (p < OVF) g_ovf[p] = rec;
}

// Process one record for prop passes.
template <bool PASS1>
__device__ __forceinline__ void do_edge(unsigned long long rec) {
    unsigned wb = (unsigned)(rec >> 38) << 6;
    if (wb) {
        int s = (int)(rec & 0x7FFFFu);
        int d = (int)((rec >> 19) & 0x7FFFFu);
        float nw = __uint_as_float(wb);          // = -w
        float2 v = PASS1 ? __ldg(&g_xs[s]) : __ldg(&g_g1[s]);
        red_add_v2(PASS1 ? &g_t1[d] : &g_t2[d], nw * v.x, nw * v.y);
    }
}

// ---------------- kernels ----------------
__global__ void k_initcur() {
    int i = blockIdx.x * blockDim.x + threadIdx.x;
    if (i < NBKT) g_bcur[i] = (unsigned)(i * CAP);
    if (i == 0) g_ovf_cnt = 0u;
}

__global__ void k_detect(const int* ei32) {
    if (threadIdx.x == 0) g_is32 = 0;
    __syncthreads();
    int found = 0;
    for (int k = threadIdx.x; k < 4000; k += 256) {
        if (ei32[(size_t)k * 7800 + 1] != 0) { found = 1; break; }
    }
    if (found) atomicOr(&g_is32, 1);
}

// Counting-sort scatter: ONE read of (src,dst,w); pack into smem; permute via
// u16 inverse-index; coalesced ordered write-out with streaming stores.
__global__ void k_scatter(const void* __restrict__ ei, const float* __restrict__ ew) {
    __shared__ unsigned int sh_hist[512];          // hist -> local cursors
    __shared__ unsigned int sh_scan[256];
    __shared__ int          sh_delta[512];
    __shared__ unsigned long long sh_stage[EPB];
    __shared__ unsigned short     sh_inv[EPB];

    const int tid = threadIdx.x;
    const int base = blockIdx.x * EPB;
    const int nrec = min(EPB, N_EDGES - base);
    const int is32 = g_is32;

    for (int i = tid; i < 512; i += 256) sh_hist[i] = 0u;
    __syncthreads();

    // Phase 1: single vectorized read of all edge data; pack + histogram.
    #pragma unroll
    for (int k = 0; k < EPB / 1024; k++) {
        int e0 = base + k * 1024 + tid * 4;
        int li = k * 1024 + tid * 4;
        if (e0 + 3 < N_EDGES) {
            int s[4], d[4];
            if (is32) {
                int4 sv = __ldg((const int4*)((const int*)ei + e0));
                int4 dv = __ldg((const int4*)((const int*)ei + N_EDGES + e0));
                s[0]=sv.x; s[1]=sv.y; s[2]=sv.z; s[3]=sv.w;
                d[0]=dv.x; d[1]=dv.y; d[2]=dv.z; d[3]=dv.w;
            } else {
                const long long* p = (const long long*)ei;
                longlong2 a = __ldg((const longlong2*)(p + e0));
                longlong2 b = __ldg((const longlong2*)(p + e0 + 2));
                longlong2 c = __ldg((const longlong2*)(p + N_EDGES + e0));
                longlong2 f = __ldg((const longlong2*)(p + N_EDGES + e0 + 2));
                s[0]=(int)a.x; s[1]=(int)a.y; s[2]=(int)b.x; s[3]=(int)b.y;
                d[0]=(int)c.x; d[1]=(int)c.y; d[2]=(int)f.x; d[3]=(int)f.y;
            }
            float4 wv = __ldg((const float4*)(ew + e0));
            float w[4] = {wv.x, wv.y, wv.z, wv.w};
            #pragma unroll
            for (int j = 0; j < 4; j++) {
                float wm = (s[j] == d[j]) ? 0.f : w[j];
                sh_stage[li + j] = pack_rec(s[j], d[j], wm);
                atomicAdd(&sh_hist[s[j] >> BSH], 1u);
            }
        } else {
            for (int j = 0; j < 4; j++) {
                int e = e0 + j;
                if (e < N_EDGES) {
                    int s = is32 ? __ldg((const int*)ei + e)
                                 : (int)__ldg((const long long*)ei + e);
                    int d = is32 ? __ldg((const int*)ei + N_EDGES + e)
                                 : (int)__ldg((const long long*)ei + N_EDGES + e);
                    float w = __ldg(ew + e);
                    if (s == d) w = 0.f;
                    sh_stage[li + j] = pack_rec(s, d, w);
                    atomicAdd(&sh_hist[s >> BSH], 1u);
                }
            }
        }
    }
    __syncthreads();

    // Phase 2: exclusive scan over 512 buckets (2 per thread).
    unsigned a0 = sh_hist[2 * tid], a1 = sh_hist[2 * tid + 1];
    sh_scan[tid] = a0 + a1;
    __syncthreads();
    for (int off = 1; off < 256; off <<= 1) {
        unsigned v = sh_scan[tid];
        unsigned add = (tid >= off) ? sh_scan[tid - off] : 0u;
        __syncthreads();
        sh_scan[tid] = v + add;
        __syncthreads();
    }
    unsigned total = sh_scan[255];
    unsigned excl = (tid == 0) ? 0u : sh_scan[tid - 1];
    unsigned p0 = excl, p1 = excl + a0;

    // Phase 3: reserve global space; local->global deltas; init local cursors.
    int b0 = 2 * tid, b1 = 2 * tid + 1;
    if (a0) { unsigned g = atomicAdd(&g_bcur[b0], a0); sh_delta[b0] = (int)g - (int)p0; }
    if (a1) { unsigned g = atomicAdd(&g_bcur[b1], a1); sh_delta[b1] = (int)g - (int)p1; }
    sh_hist[b0] = p0;
    sh_hist[b1] = p1;
    __syncthreads();

    // Phase 4: build inverse permutation (sorted position -> stage index).
    for (int i = tid; i < nrec; i += 256) {
        unsigned long long rec = sh_stage[i];
        int b = (int)((rec >> BSH) & 0x1FFu);     // bucket = s >> 10
        unsigned p = atomicAdd(&sh_hist[b], 1u);
        sh_inv[p] = (unsigned short)i;
    }
    __syncthreads();

    // Phase 5: ordered coalesced write-out (streaming stores).
    for (unsigned p = tid; p < total; p += 256) {
        unsigned long long rec = sh_stage[sh_inv[p]];
        int b = (int)((rec >> BSH) & 0x1FFu);
        unsigned gpos = (unsigned)((int)p + sh_delta[b]);
        if (gpos < (unsigned)(b + 1) * CAP) __stcs(&g_rec2[gpos], rec);
        else spill_rec(rec);
    }
}

// Degree: smem window per bucket, vectorized streaming record reads.
__global__ void k_deg2() {
    __shared__ float sh[BWIN];
    const int tid = threadIdx.x;
    const int b = blockIdx.x / NSLICE;
    const int j = blockIdx.x % NSLICE;
    unsigned cnt = g_bcur[b] - (unsigned)(b * CAP);
    if (cnt > CAP) cnt = CAP;
    unsigned chunk = (((cnt + NSLICE - 1) / NSLICE) + 1u) & ~1u;
    unsigned s0 = min(cnt, j * chunk), s1 = min(cnt, s0 + chunk);

    for (int i = tid; i < BWIN; i += 256) sh[i] = 0.f;
    __syncthreads();

    const unsigned long long* base = &g_rec2[(size_t)b * CAP];
    unsigned i = s0 + 2u * tid;
    for (; i + 1 < s1; i += 512) {
        longlong2 v = __ldcs((const longlong2*)(base + i));
        unsigned long long r0 = (unsigned long long)v.x, r1 = (unsigned long long)v.y;
        unsigned w0 = (unsigned)(r0 >> 38) << 6;
        unsigned w1 = (unsigned)(r1 >> 38) << 6;
        if (w0) atomicAdd(&sh[(int)(r0 & 0x7FFFFu) - (b << BSH)], -__uint_as_float(w0));
        if (w1) atomicAdd(&sh[(int)(r1 & 0x7FFFFu) - (b << BSH)], -__uint_as_float(w1));
    }
    if (i < s1) {
        unsigned long long r0 = __ldcs((const long long*)(base + i));
        unsigned w0 = (unsigned)(r0 >> 38) << 6;
        if (w0) atomicAdd(&sh[(int)(r0 & 0x7FFFFu) - (b << BSH)], -__uint_as_float(w0));
    }
    __syncthreads();
    for (int k = tid; k < BWIN; k += 256) {
        float v = sh[k];
        int node = (b << BSH) + k;
        if (v != 0.f && node < N_NODES) atomicAdd(&g_deg[node], v);
    }
    if (blockIdx.x == gridDim.x - 1) {
        unsigned n = g_ovf_cnt; if (n > OVF) n = OVF;
        for (unsigned q = tid; q < n; q += 256) {
            unsigned long long rec = g_ovf[q];
            unsigned wb = (unsigned)(rec >> 38) << 6;
            if (wb) atomicAdd(&g_deg[rec & 0x7FFFFu], -__uint_as_float(wb));
        }
    }
}

// dinv = rsqrt(deg); xs = dinv * x
__global__ void k_dinv(const float4* __restrict__ x) {
    int t = blockIdx.x * blockDim.x + threadIdx.x;
    int i = t * 2;
    if (i >= N_NODES) return;
    float2 dg = *(const float2*)&g_deg[i];
    float d0 = (dg.x > 0.f) ? rsqrtf(dg.x) : 0.f;
    float d1 = (dg.y > 0.f) ? rsqrtf(dg.y) : 0.f;
    *(float2*)&g_deg[i] = make_float2(d0, d1);
    float4 xv = __ldg(&x[t]);
    *(float4*)&g_xs[i] = make_float4(d0 * xv.x, d0 * xv.y, d1 * xv.z, d1 * xv.w);
}

template <bool PASS1>
__global__ void k_prop() {
    const int tid = threadIdx.x;
    const int b = blockIdx.x / NSLICE;
    const int j = blockIdx.x % NSLICE;
    unsigned cnt = g_bcur[b] - (unsigned)(b * CAP);
    if (cnt > CAP) cnt = CAP;
    unsigned chunk = (((cnt + NSLICE - 1) / NSLICE) + 1u) & ~1u;
    unsigned s0 = min(cnt, j * chunk), s1 = min(cnt, s0 + chunk);
    const unsigned long long* base = &g_rec2[(size_t)b * CAP];
    unsigned i = s0 + 2u * tid;
    for (; i + 1 < s1; i += 512) {
        longlong2 v = __ldcs((const longlong2*)(base + i));
        do_edge<PASS1>((unsigned long long)v.x);
        do_edge<PASS1>((unsigned long long)v.y);
    }
    if (i < s1) do_edge<PASS1>((unsigned long long)__ldcs((const long long*)(base + i)));

    if (blockIdx.x == gridDim.x - 1) {
        unsigned n = g_ovf_cnt; if (n > OVF) n = OVF;
        for (unsigned q = tid; q < n; q += 256) do_edge<PASS1>(g_ovf[q]);
    }
}

__global__ void k_scale2() {
    int t = blockIdx.x * blockDim.x + threadIdx.x;
    int i = t * 2;
    if (i >= N_NODES) return;
    float2 di = *(const float2*)&g_deg[i];
    float4 t1 = *(const float4*)&g_t1[i];
    float4 y1 = make_float4(di.x * t1.x, di.x * t1.y, di.y * t1.z, di.y * t1.w);
    *(float4*)&g_y1[i] = y1;
    *(float4*)&g_g1[i] = make_float4(di.x * y1.x, di.x * y1.y, di.y * y1.z, di.y * y1.w);
}

__global__ void k_final(const float2* __restrict__ x,
                        const float* __restrict__ Wz,
                        const float* __restrict__ Wh,
                        const float* __restrict__ bxz,
                        const float* __restrict__ bhz,
                        const float* __restrict__ bxh,
                        const float* __restrict__ bhh,
                        float* __restrict__ out) {
    int i = blockIdx.x * blockDim.x + threadIdx.x;
    if (i >= N_NODES) return;
    float di = g_deg[i];
    float2 T0 = __ldg(&x[i]);
    float2 T1 = g_y1[i];
    float2 t2 = g_t2[i];
    float T2x = 2.f * (di * t2.x) - T0.x;
    float T2y = 2.f * (di * t2.y) - T0.y;

    float Az = T0.x * __ldg(Wz + 0) + T0.y * __ldg(Wz + 1)
             + T1.x * __ldg(Wz + 2) + T1.y * __ldg(Wz + 3)
             + T2x  * __ldg(Wz + 4) + T2y  * __ldg(Wz + 5)
             + __ldg(bxz) + __ldg(bhz);
    float Ah = T0.x * __ldg(Wh + 0) + T0.y * __ldg(Wh + 1)
             + T1.x * __ldg(Wh + 2) + T1.y * __ldg(Wh + 3)
             + T2x  * __ldg(Wh + 4) + T2y  * __ldg(Wh + 5)
             + __ldg(bxh) + __ldg(bhh);

    float z = 1.f / (1.f + expf(-Az));
    out[i] = (1.f - z) * tanhf(Ah);
}

// ---------------- host ----------------
extern "C" void kernel_launch(void* const* d_in, const int* in_sizes, int n_in,
                              void* d_out, int out_size) {
    const float* x  = (const float*)d_in[0];
    const void*  ei = d_in[1];
    const float* ew = (const float*)d_in[2];

    int iWxz = 3, iWxh = 5, ibxz = 9, ibhz = 10, ibxh = 13, ibhh = 14; // dict order
    if (n_in >= 15 && in_sizes[4] == 1) { // signature order
        iWxz = 3; ibxz = 4; ibhz = 6; iWxh = 11; ibxh = 12; ibhh = 14;
    }
    const float* Wz  = (const float*)d_in[iWxz];
    const float* Wh  = (const float*)d_in[iWxh];
    const float* bxz = (const float*)d_in[ibxz];
    const float* bhz = (const float*)d_in[ibhz];
    const float* bxh = (const float*)d_in[ibxh];
    const float* bhh = (const float*)d_in[ibhh];

    const int TPB = 256;
    const int NB  = (N_NODES + TPB - 1) / TPB;
    const int NB2 = (N_NODES / 2 + TPB - 1) / TPB;

    void *p_deg, *p_t1, *p_t2;
    cudaGetSymbolAddress(&p_deg, g_deg);
    cudaGetSymbolAddress(&p_t1,  g_t1);
    cudaGetSymbolAddress(&p_t2,  g_t2);
    cudaMemsetAsync(p_deg, 0, N_NODES * sizeof(float), 0);
    cudaMemsetAsync(p_t1,  0, N_NODES * sizeof(float2), 0);
    cudaMemsetAsync(p_t2,  0, N_NODES * sizeof(float2), 0);

    k_initcur<<<(NBKT + TPB - 1) / TPB, TPB>>>();
    k_detect<<<1, 256>>>((const int*)ei);
    k_scatter<<<SCB, TPB>>>(ei, ew);
    k_deg2<<<NBKT * NSLICE, TPB>>>();
    k_dinv<<<NB2, TPB>>>((const float4*)x);
    k_prop<true><<<NBKT * NSLICE, TPB>>>();
    k_scale2<<<NB2, TPB>>>();
    k_prop<false><<<NBKT * NSLICE, TPB>>>();
    k_final<<<NB, TPB>>>((const float2*)x, Wz, Wh, bxz, bhz, bxh, bhh,
                         (float*)d_out);
}